// round 13
// baseline (speedup 1.0000x reference)
#include <cuda_runtime.h>
#include <math.h>

#define BE 64
#define NOCT 32
#define NSAMP 32768
#define TPB 128
#define NBLK 1184                 // 8 blocks/SM x 148 SMs -> all co-resident
#define ITEM_SAMP 1024
#define NITEMS 2048               // (be,chunk) items
#define NPART 16                  // partitions of 128 items = 2 chunks x all be
#define PITEMS (NITEMS / NPART)   // 128
#define SPT 8
#define NF4 (BE * NSAMP / 4)      // 524288 float4

// Scratch (no allocation allowed). g_wmax slots each written exactly once per
// launch (unique queue claim). Counters reset post-barrier; g_count returns
// to 0; g_phase keeps flipping -> replay-deterministic.
__device__ float g_wmax[NITEMS];  // indexed be*32 + chunk
__device__ int   g_ctrs[NPART];
__device__ int   g_count;
__device__ volatile int g_phase;

typedef unsigned long long ull;

__device__ __forceinline__ ull pk2(float x, float y) {
    ull r;
    asm("mov.b64 %0, {%1, %2};" : "=l"(r)
        : "r"(__float_as_uint(x)), "r"(__float_as_uint(y)));
    return r;
}
__device__ __forceinline__ void upk2(ull v, float& x, float& y) {
    unsigned a, b;
    asm("mov.b64 {%0, %1}, %2;" : "=r"(a), "=r"(b) : "l"(v));
    x = __uint_as_float(a);
    y = __uint_as_float(b);
}
__device__ __forceinline__ ull f2mul(ull a, ull b) {
    ull c; asm("mul.rn.f32x2 %0, %1, %2;" : "=l"(c) : "l"(a), "l"(b)); return c;
}
__device__ __forceinline__ ull f2add(ull a, ull b) {
    ull c; asm("add.rn.f32x2 %0, %1, %2;" : "=l"(c) : "l"(a), "l"(b)); return c;
}
__device__ __forceinline__ ull f2fma(ull a, ull b, ull c) {
    ull d; asm("fma.rn.f32x2 %0, %1, %2, %3;" : "=l"(d)
               : "l"(a), "l"(b), "l"(c)); return d;
}

__device__ __forceinline__ void grid_barrier() {
    __syncthreads();
    if (threadIdx.x == 0) {
        int ph = g_phase;
        __threadfence();                           // release
        if (atomicAdd(&g_count, 1) == NBLK - 1) {
            g_count = 0;
            __threadfence();
            g_phase = ph ^ 1;
        } else {
            while (g_phase == ph) { __nanosleep(32); }
        }
        __threadfence();                           // acquire
    }
    __syncthreads();
}

// fl32(f*t) phase -> magic round -> exact 2-FMA Cody-Waite -> MUFU sin.
// Lanewise IEEE RN, bit-identical to the scalar reference path.
#define OSC_STEP(F2, A2, TPj, ACCj)                                   \
    {                                                                 \
        ull p2 = f2mul((F2), (TPj));                                  \
        ull q2 = f2fma(p2, INV2PI2, MAGIC2);                          \
        ull k2 = f2add(q2, NMAG2);                                    \
        ull r2 = f2fma(k2, NHI2, p2);                                 \
        r2     = f2fma(k2, NLO2, r2);                                 \
        float r0_, r1_; upk2(r2, r0_, r1_);                           \
        ull s2 = pk2(__sinf(r0_), __sinf(r1_));                       \
        (ACCj) = f2fma(s2, (A2), (ACCj));                             \
    }

__global__ void __launch_bounds__(TPB, 8)
fused_kernel(const float* __restrict__ f0_in,
             const float* __restrict__ dec_in,
             const float* __restrict__ sp_in,
             float* __restrict__ out) {
    __shared__ ull   sfp[NOCT];      // pre-packed {f, f}
    __shared__ ull   sap[NOCT];      // pre-packed {a, a}
    __shared__ int   snact;
    __shared__ float wm[TPB / 32];
    __shared__ int   s_loc;
    __shared__ float sinv[BE];

    const int tid  = threadIdx.x;
    const int lane = tid & 31;
    const int part = blockIdx.x & (NPART - 1);     // equal-weight partition

    const float INV2PI = 0.15915494309189535f;
    const float MAGIC  = 12582912.0f;              // 1.5 * 2^23
    const float HI     = 6.2831855f;               // fl32(2*pi)
    const float LO     = (float)(6.283185307179586476925286766559
                                 - (double)6.2831855f);
    const ull INV2PI2 = pk2(INV2PI, INV2PI);
    const ull MAGIC2  = pk2(MAGIC, MAGIC);
    const ull NMAG2   = pk2(-MAGIC, -MAGIC);
    const ull NHI2    = pk2(-HI, -HI);
    const ull NLO2    = pk2(-LO, -LO);

    // ---- Phase 1: per-partition queue (128 items = 2 chunks x all 64 be) ----
    for (;;) {
        __syncthreads();                           // protect s_loc/sfp/wm
        if (tid == 0) s_loc = atomicAdd(&g_ctrs[part], 1);
        __syncthreads();
        const int loc = s_loc;
        if (loc >= PITEMS) break;                  // uniform exit

        const int be    = loc & (BE - 1);          // be-interleaved in part
        const int chunk = (part << 1) + (loc >> 6);

        // per-item setup: warp 0, lane-parallel, own be only (phase path
        // bit-exact: lane o repeats the sequential f32 fadd chain, len o+1)
        if (tid < 32) {
            const float MINF   = (float)(20.0 / 11025.0);
            const float FRANGE = (float)(3000.0 / 11025.0 - 20.0 / 11025.0);
            const float PI_F   = (float)3.14159265358979323846;
            const float RESF   = (float)((1.0 - 0.01) * 0.99);

            float f0  = fabsf(f0_in[be]);
            float fsc = __fmul_rn(__fadd_rn(MINF, __fmul_rn(f0, FRANGE)), PI_F);
            float sp  = sp_in[be];

            float x  = dec_in[be];
            float s1 = 1.0f / (1.0f + expf(-x));
            float s2 = 1.0f / (1.0f + expf(-s1));
            float d  = __fadd_rn(0.01f, __fmul_rn(s2, RESF));
            float ld = logf(__fadd_rn(d, 1e-12f));

            float fac = 0.0f;
            #pragma unroll
            for (int i = 0; i < NOCT; i++)
                if (i <= lane) fac = __fadd_rn(fac, sp);  // seq cumsum
            float f0s = __fmul_rn(fsc, fac);
            float amp = __expf((float)(lane + 1) * ld);   // amp err ~1e-6 ok
            sfp[lane] = pk2(f0s, f0s);
            sap[lane] = pk2(amp, amp);
            unsigned bal = __ballot_sync(0xFFFFFFFFu, f0s < 1.0f);
            if (lane == 0) snact = __popc(bal);           // prefix mask
        }
        __syncthreads();
        const int nact = snact;

        // thread owns samples chunk*1024 + g*512 + tid*4 + j (g=0..1,j=0..3)
        const float tb = (float)(chunk * ITEM_SAMP + tid * 4 + 1);
        ull TP[SPT / 2];
        TP[0] = pk2(tb,          tb + 1.0f);
        TP[1] = pk2(tb + 2.0f,   tb + 3.0f);
        TP[2] = pk2(tb + 512.0f, tb + 513.0f);
        TP[3] = pk2(tb + 514.0f, tb + 515.0f);

        ull ACC[SPT / 2];
        #pragma unroll
        for (int j = 0; j < SPT / 2; j++) ACC[j] = pk2(0.0f, 0.0f);

        // octave loop unrolled x2: 8 independent sin chains in flight
        int o = 0;
        for (; o + 1 < nact; o += 2) {
            const ull fA = sfp[o],     aA = sap[o];
            const ull fB = sfp[o + 1], aB = sap[o + 1];
            #pragma unroll
            for (int j = 0; j < SPT / 2; j++) {
                OSC_STEP(fA, aA, TP[j], ACC[j]);
                OSC_STEP(fB, aB, TP[j], ACC[j]);
            }
        }
        if (o < nact) {
            const ull fA = sfp[o], aA = sap[o];
            #pragma unroll
            for (int j = 0; j < SPT / 2; j++)
                OSC_STEP(fA, aA, TP[j], ACC[j]);
        }

        float v0, v1, v2, v3, v4, v5, v6, v7;
        upk2(ACC[0], v0, v1); upk2(ACC[1], v2, v3);
        upk2(ACC[2], v4, v5); upk2(ACC[3], v6, v7);

        float4* o4 = (float4*)(out + be * NSAMP + chunk * ITEM_SAMP);
        float4 w0; w0.x = v0; w0.y = v1; w0.z = v2; w0.w = v3;
        float4 w1; w1.x = v4; w1.y = v5; w1.z = v6; w1.w = v7;
        o4[tid]       = w0;
        o4[tid + TPB] = w1;

        float m = fmaxf(fmaxf(fmaxf(fabsf(v0), fabsf(v1)),
                              fmaxf(fabsf(v2), fabsf(v3))),
                        fmaxf(fmaxf(fabsf(v4), fabsf(v5)),
                              fmaxf(fabsf(v6), fabsf(v7))));
        #pragma unroll
        for (int off = 16; off > 0; off >>= 1)
            m = fmaxf(m, __shfl_xor_sync(0xFFFFFFFFu, m, off));
        if (lane == 0) wm[tid >> 5] = m;
        __syncthreads();
        if (tid == 0) {
            float mm = fmaxf(fmaxf(wm[0], wm[1]), fmaxf(wm[2], wm[3]));
            g_wmax[(be << 5) + chunk] = mm;       // unique slot
        }
    }

    grid_barrier();   // all osc stores + g_wmax visible chip-wide

    if (blockIdx.x == 0 && tid < NPART) g_ctrs[tid] = 0;   // replay reset

    // ---- Phase 2a: per-be inverse max (64 threads, 32 MLP'd L2 loads) ----
    if (tid < BE) {
        float m = 0.0f;
        #pragma unroll
        for (int j = 0; j < NSAMP / ITEM_SAMP; j++)
            m = fmaxf(m, __ldcg(&g_wmax[(tid << 5) + j]));
        sinv[tid] = 1.0f / (m + 1e-8f);
    }
    __syncthreads();

    // ---- Phase 2b: grid-stride normalize, full-chip parallelism ----
    float4* o4 = (float4*)out;
    for (int i = blockIdx.x * TPB + tid; i < NF4; i += NBLK * TPB) {
        float inv = sinv[i >> 13];                  // 8192 float4 per be
        float4 w = __ldcg(o4 + i);                  // bypass stale L1
        w.x *= inv; w.y *= inv; w.z *= inv; w.w *= inv;
        __stcg(o4 + i, w);
    }
}

extern "C" void kernel_launch(void* const* d_in, const int* in_sizes, int n_in,
                              void* d_out, int out_size) {
    const float* f0  = (const float*)d_in[0];
    const float* dec = (const float*)d_in[1];
    const float* sp  = (const float*)d_in[2];
    float* out = (float*)d_out;

    fused_kernel<<<NBLK, TPB>>>(f0, dec, sp, out);
}

// round 14
// speedup vs baseline: 5.2209x; 5.2209x over previous
#include <cuda_runtime.h>
#include <math.h>

#define BE 64
#define NOCT 32
#define NSAMP 32768
#define TPB 128
#define ITEM_SAMP 1024
#define NBLK (BE * NSAMP / ITEM_SAMP)   // 2048 blocks, 1 item each
#define SPT 8

// Per-item max scratch: every slot written exactly once per launch.
__device__ float g_wmax[NBLK];

typedef unsigned long long ull;

__device__ __forceinline__ ull pk2(float x, float y) {
    ull r;
    asm("mov.b64 %0, {%1, %2};" : "=l"(r)
        : "r"(__float_as_uint(x)), "r"(__float_as_uint(y)));
    return r;
}
__device__ __forceinline__ void upk2(ull v, float& x, float& y) {
    unsigned a, b;
    asm("mov.b64 {%0, %1}, %2;" : "=r"(a), "=r"(b) : "l"(v));
    x = __uint_as_float(a);
    y = __uint_as_float(b);
}
__device__ __forceinline__ ull f2mul(ull a, ull b) {
    ull c; asm("mul.rn.f32x2 %0, %1, %2;" : "=l"(c) : "l"(a), "l"(b)); return c;
}
__device__ __forceinline__ ull f2add(ull a, ull b) {
    ull c; asm("add.rn.f32x2 %0, %1, %2;" : "=l"(c) : "l"(a), "l"(b)); return c;
}
__device__ __forceinline__ ull f2fma(ull a, ull b, ull c) {
    ull d; asm("fma.rn.f32x2 %0, %1, %2, %3;" : "=l"(d)
               : "l"(a), "l"(b), "l"(c)); return d;
}

// fl32(f*t) phase -> magic round -> exact 2-FMA Cody-Waite -> MUFU sin.
// Lanewise IEEE RN, bit-identical to the scalar reference path.
#define OSC_STEP(F2, A2, TPj, ACCj)                                   \
    {                                                                 \
        ull p2 = f2mul((F2), (TPj));                                  \
        ull q2 = f2fma(p2, INV2PI2, MAGIC2);                          \
        ull k2 = f2add(q2, NMAG2);                                    \
        ull r2 = f2fma(k2, NHI2, p2);                                 \
        r2     = f2fma(k2, NLO2, r2);                                 \
        float r0_, r1_; upk2(r2, r0_, r1_);                           \
        ull s2 = pk2(__sinf(r0_), __sinf(r1_));                      \
        (ACCj) = f2fma(s2, (A2), (ACCj));                             \
    }

// ---------------------------------------------------------------------------
// Kernel A: oscillator bank (R8 skeleton). Block = one (be, 1024-sample
// chunk), be-interleaved across blockIdx so every dispatch wave averages the
// per-be octave-count imbalance. Octave loop unrolled x2 (8 sin chains in
// flight); f/a pairs pre-packed in shared for single LDS.64 operand loads.
// ---------------------------------------------------------------------------
__global__ void __launch_bounds__(TPB)
osc_kernel(const float* __restrict__ f0_in,
           const float* __restrict__ dec_in,
           const float* __restrict__ sp_in,
           float* __restrict__ out) {
    __shared__ ull   sfp[NOCT];      // pre-packed {f, f}
    __shared__ ull   sap[NOCT];      // pre-packed {a, a}
    __shared__ int   snact;
    __shared__ float wm[TPB / 32];

    const int be    = blockIdx.x & (BE - 1);
    const int chunk = blockIdx.x >> 6;
    const int tid   = threadIdx.x;
    const int lane  = tid & 31;

    // setup: warp 0, lane-parallel, own be only (phase path bit-exact:
    // lane o repeats the same sequential f32 fadd chain of length o+1)
    if (tid < 32) {
        const float MINF   = (float)(20.0 / 11025.0);
        const float FRANGE = (float)(3000.0 / 11025.0 - 20.0 / 11025.0);
        const float PI_F   = (float)3.14159265358979323846;
        const float RESF   = (float)((1.0 - 0.01) * 0.99);

        float f0  = fabsf(f0_in[be]);
        float fsc = __fmul_rn(__fadd_rn(MINF, __fmul_rn(f0, FRANGE)), PI_F);
        float sp  = sp_in[be];

        float x  = dec_in[be];
        float s1 = 1.0f / (1.0f + expf(-x));
        float s2 = 1.0f / (1.0f + expf(-s1));
        float d  = __fadd_rn(0.01f, __fmul_rn(s2, RESF));
        float ld = logf(__fadd_rn(d, 1e-12f));

        float fac = 0.0f;
        #pragma unroll
        for (int i = 0; i < NOCT; i++)
            if (i <= lane) fac = __fadd_rn(fac, sp);   // predicated seq cumsum
        float f0s = __fmul_rn(fsc, fac);
        float amp = __expf((float)(lane + 1) * ld);    // amp err ~1e-6, safe
        sfp[lane] = pk2(f0s, f0s);
        sap[lane] = pk2(amp, amp);
        unsigned bal = __ballot_sync(0xFFFFFFFFu, f0s < 1.0f);
        if (lane == 0) snact = __popc(bal);            // monotone prefix mask
    }
    __syncthreads();
    const int nact = snact;

    // thread owns samples chunk*1024 + g*512 + tid*4 + j (g=0..1, j=0..3)
    const float tb = (float)(chunk * ITEM_SAMP + tid * 4 + 1);
    ull TP[SPT / 2];
    TP[0] = pk2(tb,          tb + 1.0f);
    TP[1] = pk2(tb + 2.0f,   tb + 3.0f);
    TP[2] = pk2(tb + 512.0f, tb + 513.0f);
    TP[3] = pk2(tb + 514.0f, tb + 515.0f);

    const float INV2PI = 0.15915494309189535f;
    const float MAGIC  = 12582912.0f;                  // 1.5 * 2^23
    const float HI     = 6.2831855f;                   // fl32(2*pi)
    const float LO     = (float)(6.283185307179586476925286766559
                                 - (double)6.2831855f);
    const ull INV2PI2 = pk2(INV2PI, INV2PI);
    const ull MAGIC2  = pk2(MAGIC, MAGIC);
    const ull NMAG2   = pk2(-MAGIC, -MAGIC);
    const ull NHI2    = pk2(-HI, -HI);
    const ull NLO2    = pk2(-LO, -LO);

    ull ACC[SPT / 2];
    #pragma unroll
    for (int j = 0; j < SPT / 2; j++) ACC[j] = pk2(0.0f, 0.0f);

    // octave loop unrolled x2: 8 independent sin chains in flight
    int o = 0;
    for (; o + 1 < nact; o += 2) {
        const ull fA = sfp[o],     aA = sap[o];
        const ull fB = sfp[o + 1], aB = sap[o + 1];
        #pragma unroll
        for (int j = 0; j < SPT / 2; j++) {
            OSC_STEP(fA, aA, TP[j], ACC[j]);
            OSC_STEP(fB, aB, TP[j], ACC[j]);
        }
    }
    if (o < nact) {
        const ull fA = sfp[o], aA = sap[o];
        #pragma unroll
        for (int j = 0; j < SPT / 2; j++)
            OSC_STEP(fA, aA, TP[j], ACC[j]);
    }

    float v0, v1, v2, v3, v4, v5, v6, v7;
    upk2(ACC[0], v0, v1); upk2(ACC[1], v2, v3);
    upk2(ACC[2], v4, v5); upk2(ACC[3], v6, v7);

    float4* o4 = (float4*)(out + be * NSAMP + chunk * ITEM_SAMP);
    float4 w0; w0.x = v0; w0.y = v1; w0.z = v2; w0.w = v3;
    float4 w1; w1.x = v4; w1.y = v5; w1.z = v6; w1.w = v7;
    o4[tid]       = w0;
    o4[tid + TPB] = w1;

    // block max-abs -> one slot
    float m = fmaxf(fmaxf(fmaxf(fabsf(v0), fabsf(v1)),
                          fmaxf(fabsf(v2), fabsf(v3))),
                    fmaxf(fmaxf(fabsf(v4), fabsf(v5)),
                          fmaxf(fabsf(v6), fabsf(v7))));
    #pragma unroll
    for (int off = 16; off > 0; off >>= 1)
        m = fmaxf(m, __shfl_xor_sync(0xFFFFFFFFu, m, off));
    if (lane == 0) wm[tid >> 5] = m;
    __syncthreads();
    if (tid == 0) {
        float mm = fmaxf(fmaxf(wm[0], wm[1]), fmaxf(wm[2], wm[3]));
        g_wmax[blockIdx.x] = mm;
    }
}

// ---------------------------------------------------------------------------
// Kernel B: reduce 32 chunk-maxes per be (slots be + 64*chunk), normalize
// in place with 4x float4 per thread. (Proven config; overhead-floored.)
// ---------------------------------------------------------------------------
__global__ void __launch_bounds__(256)
norm_kernel(float4* __restrict__ out4) {
    const int be   = blockIdx.y;
    const int seg  = blockIdx.x;                 // 0..7, each 1024 float4
    const int tid  = threadIdx.x;
    const int lane = tid & 31;

    float v = g_wmax[(lane << 6) + be];          // 32 chunk maxes
    #pragma unroll
    for (int off = 16; off > 0; off >>= 1)
        v = fmaxf(v, __shfl_xor_sync(0xFFFFFFFFu, v, off));
    const float inv = 1.0f / (v + 1e-8f);

    float4* p = out4 + be * (NSAMP / 4) + seg * 1024;
    float4 w0 = p[tid];
    float4 w1 = p[tid + 256];
    float4 w2 = p[tid + 512];
    float4 w3 = p[tid + 768];
    w0.x *= inv; w0.y *= inv; w0.z *= inv; w0.w *= inv;
    w1.x *= inv; w1.y *= inv; w1.z *= inv; w1.w *= inv;
    w2.x *= inv; w2.y *= inv; w2.z *= inv; w2.w *= inv;
    w3.x *= inv; w3.y *= inv; w3.z *= inv; w3.w *= inv;
    p[tid]       = w0;
    p[tid + 256] = w1;
    p[tid + 512] = w2;
    p[tid + 768] = w3;
}

extern "C" void kernel_launch(void* const* d_in, const int* in_sizes, int n_in,
                              void* d_out, int out_size) {
    const float* f0  = (const float*)d_in[0];
    const float* dec = (const float*)d_in[1];
    const float* sp  = (const float*)d_in[2];
    float* out = (float*)d_out;

    osc_kernel<<<NBLK, TPB>>>(f0, dec, sp, out);
    dim3 gB(8, BE);
    norm_kernel<<<gB, 256>>>((float4*)out);
}

// round 15
// speedup vs baseline: 5.2386x; 1.0034x over previous
#include <cuda_runtime.h>
#include <math.h>

#define BE 64
#define NOCT 32
#define NSAMP 32768
#define TPB 64
#define ITEM_SAMP 512
#define NBLK (BE * NSAMP / ITEM_SAMP)   // 4096 blocks, 1 item each
#define NCHUNK (NSAMP / ITEM_SAMP)      // 64 chunks per be
#define SPT 8

// Per-item max scratch: every slot written exactly once per launch.
__device__ float g_wmax[NBLK];

typedef unsigned long long ull;

__device__ __forceinline__ ull pk2(float x, float y) {
    ull r;
    asm("mov.b64 %0, {%1, %2};" : "=l"(r)
        : "r"(__float_as_uint(x)), "r"(__float_as_uint(y)));
    return r;
}
__device__ __forceinline__ void upk2(ull v, float& x, float& y) {
    unsigned a, b;
    asm("mov.b64 {%0, %1}, %2;" : "=r"(a), "=r"(b) : "l"(v));
    x = __uint_as_float(a);
    y = __uint_as_float(b);
}
__device__ __forceinline__ ull f2mul(ull a, ull b) {
    ull c; asm("mul.rn.f32x2 %0, %1, %2;" : "=l"(c) : "l"(a), "l"(b)); return c;
}
__device__ __forceinline__ ull f2add(ull a, ull b) {
    ull c; asm("add.rn.f32x2 %0, %1, %2;" : "=l"(c) : "l"(a), "l"(b)); return c;
}
__device__ __forceinline__ ull f2fma(ull a, ull b, ull c) {
    ull d; asm("fma.rn.f32x2 %0, %1, %2, %3;" : "=l"(d)
               : "l"(a), "l"(b), "l"(c)); return d;
}

// fl32(f*t) phase -> magic round -> exact 2-FMA Cody-Waite -> MUFU sin.
// Lanewise IEEE RN, bit-identical to the scalar reference path.
#define OSC_STEP(F2, A2, TPj, ACCj)                                   \
    {                                                                 \
        ull p2 = f2mul((F2), (TPj));                                  \
        ull q2 = f2fma(p2, INV2PI2, MAGIC2);                          \
        ull k2 = f2add(q2, NMAG2);                                    \
        ull r2 = f2fma(k2, NHI2, p2);                                 \
        r2     = f2fma(k2, NLO2, r2);                                 \
        float r0_, r1_; upk2(r2, r0_, r1_);                           \
        ull s2 = pk2(__sinf(r0_), __sinf(r1_));                       \
        (ACCj) = f2fma(s2, (A2), (ACCj));                             \
    }

// ---------------------------------------------------------------------------
// Kernel A: oscillator bank. Block = one (be, 512-sample chunk),
// be-interleaved across blockIdx. Small work quantum halves the straggler
// tail; 21 resident blocks/SM (42 warps) raises occupancy vs TPB=128.
// Octave loop unrolled x2 (8 sin chains in flight); f/a pairs pre-packed.
// ---------------------------------------------------------------------------
__global__ void __launch_bounds__(TPB)
osc_kernel(const float* __restrict__ f0_in,
           const float* __restrict__ dec_in,
           const float* __restrict__ sp_in,
           float* __restrict__ out) {
    __shared__ ull   sfp[NOCT];      // pre-packed {f, f}
    __shared__ ull   sap[NOCT];      // pre-packed {a, a}
    __shared__ int   snact;
    __shared__ float wm[TPB / 32];

    const int be    = blockIdx.x & (BE - 1);
    const int chunk = blockIdx.x >> 6;           // 0..63
    const int tid   = threadIdx.x;
    const int lane  = tid & 31;

    // setup: warp 0, lane-parallel, own be only (phase path bit-exact:
    // lane o repeats the same sequential f32 fadd chain of length o+1)
    if (tid < 32) {
        const float MINF   = (float)(20.0 / 11025.0);
        const float FRANGE = (float)(3000.0 / 11025.0 - 20.0 / 11025.0);
        const float PI_F   = (float)3.14159265358979323846;
        const float RESF   = (float)((1.0 - 0.01) * 0.99);

        float f0  = fabsf(f0_in[be]);
        float fsc = __fmul_rn(__fadd_rn(MINF, __fmul_rn(f0, FRANGE)), PI_F);
        float sp  = sp_in[be];

        float x  = dec_in[be];
        float s1 = 1.0f / (1.0f + expf(-x));
        float s2 = 1.0f / (1.0f + expf(-s1));
        float d  = __fadd_rn(0.01f, __fmul_rn(s2, RESF));
        float ld = logf(__fadd_rn(d, 1e-12f));

        float fac = 0.0f;
        #pragma unroll
        for (int i = 0; i < NOCT; i++)
            if (i <= lane) fac = __fadd_rn(fac, sp);   // predicated seq cumsum
        float f0s = __fmul_rn(fsc, fac);
        float amp = __expf((float)(lane + 1) * ld);    // amp err ~1e-6, safe
        sfp[lane] = pk2(f0s, f0s);
        sap[lane] = pk2(amp, amp);
        unsigned bal = __ballot_sync(0xFFFFFFFFu, f0s < 1.0f);
        if (lane == 0) snact = __popc(bal);            // monotone prefix mask
    }
    __syncthreads();
    const int nact = snact;

    // thread owns samples chunk*512 + g*256 + tid*4 + j (g=0..1, j=0..3)
    const float tb = (float)(chunk * ITEM_SAMP + tid * 4 + 1);
    ull TP[SPT / 2];
    TP[0] = pk2(tb,          tb + 1.0f);
    TP[1] = pk2(tb + 2.0f,   tb + 3.0f);
    TP[2] = pk2(tb + 256.0f, tb + 257.0f);
    TP[3] = pk2(tb + 258.0f, tb + 259.0f);

    const float INV2PI = 0.15915494309189535f;
    const float MAGIC  = 12582912.0f;                  // 1.5 * 2^23
    const float HI     = 6.2831855f;                   // fl32(2*pi)
    const float LO     = (float)(6.283185307179586476925286766559
                                 - (double)6.2831855f);
    const ull INV2PI2 = pk2(INV2PI, INV2PI);
    const ull MAGIC2  = pk2(MAGIC, MAGIC);
    const ull NMAG2   = pk2(-MAGIC, -MAGIC);
    const ull NHI2    = pk2(-HI, -HI);
    const ull NLO2    = pk2(-LO, -LO);

    ull ACC[SPT / 2];
    #pragma unroll
    for (int j = 0; j < SPT / 2; j++) ACC[j] = pk2(0.0f, 0.0f);

    // octave loop unrolled x2: 8 independent sin chains in flight
    int o = 0;
    for (; o + 1 < nact; o += 2) {
        const ull fA = sfp[o],     aA = sap[o];
        const ull fB = sfp[o + 1], aB = sap[o + 1];
        #pragma unroll
        for (int j = 0; j < SPT / 2; j++) {
            OSC_STEP(fA, aA, TP[j], ACC[j]);
            OSC_STEP(fB, aB, TP[j], ACC[j]);
        }
    }
    if (o < nact) {
        const ull fA = sfp[o], aA = sap[o];
        #pragma unroll
        for (int j = 0; j < SPT / 2; j++)
            OSC_STEP(fA, aA, TP[j], ACC[j]);
    }

    float v0, v1, v2, v3, v4, v5, v6, v7;
    upk2(ACC[0], v0, v1); upk2(ACC[1], v2, v3);
    upk2(ACC[2], v4, v5); upk2(ACC[3], v6, v7);

    float4* o4 = (float4*)(out + be * NSAMP + chunk * ITEM_SAMP);
    float4 w0; w0.x = v0; w0.y = v1; w0.z = v2; w0.w = v3;
    float4 w1; w1.x = v4; w1.y = v5; w1.z = v6; w1.w = v7;
    o4[tid]       = w0;
    o4[tid + TPB] = w1;

    // block max-abs -> one slot
    float m = fmaxf(fmaxf(fmaxf(fabsf(v0), fabsf(v1)),
                          fmaxf(fabsf(v2), fabsf(v3))),
                    fmaxf(fmaxf(fabsf(v4), fabsf(v5)),
                          fmaxf(fabsf(v6), fabsf(v7))));
    #pragma unroll
    for (int off = 16; off > 0; off >>= 1)
        m = fmaxf(m, __shfl_xor_sync(0xFFFFFFFFu, m, off));
    if (lane == 0) wm[tid >> 5] = m;
    __syncthreads();
    if (tid == 0) {
        g_wmax[blockIdx.x] = fmaxf(wm[0], wm[1]);
    }
}

// ---------------------------------------------------------------------------
// Kernel B: reduce 64 chunk-maxes per be (slots be + 64*chunk; lanes cover
// 32 each, 2 per lane), normalize in place with 4x float4 per thread.
// ---------------------------------------------------------------------------
__global__ void __launch_bounds__(256)
norm_kernel(float4* __restrict__ out4) {
    const int be   = blockIdx.y;
    const int seg  = blockIdx.x;                 // 0..7, each 1024 float4
    const int tid  = threadIdx.x;
    const int lane = tid & 31;

    float v = fmaxf(g_wmax[(lane << 6) + be],
                    g_wmax[((lane + 32) << 6) + be]);   // 64 chunk maxes
    #pragma unroll
    for (int off = 16; off > 0; off >>= 1)
        v = fmaxf(v, __shfl_xor_sync(0xFFFFFFFFu, v, off));
    const float inv = 1.0f / (v + 1e-8f);

    float4* p = out4 + be * (NSAMP / 4) + seg * 1024;
    float4 w0 = p[tid];
    float4 w1 = p[tid + 256];
    float4 w2 = p[tid + 512];
    float4 w3 = p[tid + 768];
    w0.x *= inv; w0.y *= inv; w0.z *= inv; w0.w *= inv;
    w1.x *= inv; w1.y *= inv; w1.z *= inv; w1.w *= inv;
    w2.x *= inv; w2.y *= inv; w2.z *= inv; w2.w *= inv;
    w3.x *= inv; w3.y *= inv; w3.z *= inv; w3.w *= inv;
    p[tid]       = w0;
    p[tid + 256] = w1;
    p[tid + 512] = w2;
    p[tid + 768] = w3;
}

extern "C" void kernel_launch(void* const* d_in, const int* in_sizes, int n_in,
                              void* d_out, int out_size) {
    const float* f0  = (const float*)d_in[0];
    const float* dec = (const float*)d_in[1];
    const float* sp  = (const float*)d_in[2];
    float* out = (float*)d_out;

    osc_kernel<<<NBLK, TPB>>>(f0, dec, sp, out);
    dim3 gB(8, BE);
    norm_kernel<<<gB, 256>>>((float4*)out);
}